// round 12
// baseline (speedup 1.0000x reference)
#include <cuda_runtime.h>

// Shapes (fixed)
#define BB 256
#define NN 16
#define OBS 64
#define ACT 8
#define DD 128
#define HH 64
#define II 72
#define NF 192

// 16B-aligned padded strides (floats)
#define WE_S 76
#define W1_S 196
#define ST_S 68
#define AC_S 12
#define E_S  132
#define WT_S 17
#define HV_S 68

// bank swizzle: rows n>=8 get their column-quads XOR'd by 4 words (16B)
#define SW(n) (((n) & 8) >> 1)

// float offsets into dynamic smem (all float4-aligned)
#define OFF_WEU 0
#define SZ_WEU  12544                 /* max(128*76=9728, 64*196=12544) */
#define OFF_WA  (OFF_WEU + SZ_WEU)
#define OFF_W2  (OFF_WA + 2 * DD)
#define OFF_ST  (OFF_W2 + HH)
#define OFF_AC  (OFF_ST + NN * ST_S)
#define OFF_PO  (OFF_AC + NN * AC_S)
#define OFF_TA  (OFF_PO + NN * AC_S)
#define OFF_DE  (OFF_TA + NN * E_S)
#define OFF_W   (OFF_DE + NN * E_S)
#define OFF_T1  (OFF_W  + NN * WT_S)
#define OFF_V1  (OFF_T1 + NN * HV_S)
#define OFF_U   (OFF_V1 + NN * HV_S)
#define OFF_T2  (OFF_U  + NN * HV_S)
#define OFF_V2  (OFF_T2 + NN * HV_S)
#define OFF_SSRC (OFF_V2 + NN * HV_S)
#define OFF_SDST (OFF_SSRC + NN)
#define SMEM_FLOATS (OFF_SDST + NN)

typedef unsigned long long u64;

__device__ __forceinline__ float lrelu(float x) {
    return fmaxf(x, 0.01f * x);
}

__device__ __forceinline__ float fast_tanh(float x) {
    float cx = fminf(fmaxf(x, -10.0f), 10.0f);
    float e = __expf(2.0f * cx);
    return __fdividef(e - 1.0f, e + 1.0f);
}

__device__ __forceinline__ float dot4(float4 a, float4 b, float acc) {
    acc = fmaf(a.x, b.x, acc);
    acc = fmaf(a.y, b.y, acc);
    acc = fmaf(a.z, b.z, acc);
    acc = fmaf(a.w, b.w, acc);
    return acc;
}

// packed fp32x2 FMA (sm_100+)
__device__ __forceinline__ u64 fma2(u64 a, u64 b, u64 c) {
    u64 d;
    asm("fma.rn.f32x2 %0, %1, %2, %3;" : "=l"(d) : "l"(a), "l"(b), "l"(c));
    return d;
}
__device__ __forceinline__ float hadd2(u64 v) {
    float lo, hi;
    asm("mov.b64 {%0, %1}, %2;" : "=f"(lo), "=f"(hi) : "l"(v));
    return lo + hi;
}

__global__ void __launch_bounds__(256, 2)
gac_kernel(const float* __restrict__ g_st, const float* __restrict__ g_po,
           const float* __restrict__ g_ac, const float* __restrict__ g_We,
           const float* __restrict__ g_Wa, const float* __restrict__ g_W1,
           const float* __restrict__ g_W2, float* __restrict__ out,
           int write_w)
{
    extern __shared__ float sm[];
    float* We  = sm + OFF_WEU;   // [128][76] phase 1
    float* W1  = sm + OFF_WEU;   // [64][196] phase 3+ (union)
    float* Wa  = sm + OFF_WA;
    float* W2s = sm + OFF_W2;
    float* st  = sm + OFF_ST;
    float* ac  = sm + OFF_AC;
    float* po  = sm + OFF_PO;
    float* ta  = sm + OFF_TA;
    float* de  = sm + OFF_DE;
    float* w   = sm + OFF_W;
    float* T1  = sm + OFF_T1;
    float* V1  = sm + OFF_V1;
    float* U   = sm + OFF_U;
    float* T2  = sm + OFF_T2;
    float* V2  = sm + OFF_V2;
    float* ssrc = sm + OFF_SSRC;
    float* sdst = sm + OFF_SDST;

    const int t = threadIdx.x;
    const int b = blockIdx.x;

    // ---- P0: cooperative float4 loads ----
    {
        #pragma unroll
        for (int i = 0; i < 9; i++) {
            int e = (t + i * 256) * 4;
            int r = e / II, c = e - r * II;
            *(float4*)&We[r * WE_S + c] = *(const float4*)&g_We[e];
        }
        if (t < 64) *(float4*)&Wa[t * 4] = *(const float4*)&g_Wa[t * 4];
        if (t < 16) *(float4*)&W2s[t * 4] = *(const float4*)&g_W2[t * 4];
        {
            int r = t >> 4, c = (t & 15) * 4;
            *(float4*)&st[r * ST_S + (c ^ SW(r))] = *(const float4*)&g_st[b * NN * OBS + t * 4];
        }
        if (t < 32) {
            int r = t >> 1, c = (t & 1) * 4;
            *(float4*)&ac[r * AC_S + c] = *(const float4*)&g_ac[b * NN * ACT + t * 4];
            *(float4*)&po[r * AC_S + c] = *(const float4*)&g_po[b * NN * ACT + t * 4];
        }
        if (t < NN) { ssrc[t] = 0.0f; sdst[t] = 0.0f; }
    }
    __syncthreads();

    // ---- P1: embeddings, 2n x 4d tiles, packed f32x2 inner math ----
    {
        const int np = t & 7;
        const int n0 = np * 2, n1 = n0 + 1;
        const int d0 = (t >> 3) * 4;
        const int sw = SW(n0);

        u64 sa0[4], sa1[4], sp0[4], sp1[4];
        #pragma unroll
        for (int u = 0; u < 4; u++) { sa0[u] = 0ull; sa1[u] = 0ull; }
        #pragma unroll
        for (int k = 0; k < OBS; k += 4) {
            ulonglong2 x0 = *(const ulonglong2*)&st[n0 * ST_S + (k ^ sw)];
            ulonglong2 x1 = *(const ulonglong2*)&st[n1 * ST_S + (k ^ sw)];
            #pragma unroll
            for (int u = 0; u < 4; u++) {
                ulonglong2 wv = *(const ulonglong2*)&We[(d0 + u) * WE_S + k];
                sa0[u] = fma2(wv.x, x0.x, sa0[u]);
                sa0[u] = fma2(wv.y, x0.y, sa0[u]);
                sa1[u] = fma2(wv.x, x1.x, sa1[u]);
                sa1[u] = fma2(wv.y, x1.y, sa1[u]);
            }
        }
        #pragma unroll
        for (int u = 0; u < 4; u++) { sp0[u] = sa0[u]; sp1[u] = sa1[u]; }
        #pragma unroll
        for (int k = 0; k < ACT; k += 4) {
            ulonglong2 xa0 = *(const ulonglong2*)&ac[n0 * AC_S + k];
            ulonglong2 xa1 = *(const ulonglong2*)&ac[n1 * AC_S + k];
            ulonglong2 xp0 = *(const ulonglong2*)&po[n0 * AC_S + k];
            ulonglong2 xp1 = *(const ulonglong2*)&po[n1 * AC_S + k];
            #pragma unroll
            for (int u = 0; u < 4; u++) {
                ulonglong2 wv = *(const ulonglong2*)&We[(d0 + u) * WE_S + OBS + k];
                sa0[u] = fma2(wv.x, xa0.x, sa0[u]);
                sa0[u] = fma2(wv.y, xa0.y, sa0[u]);
                sa1[u] = fma2(wv.x, xa1.x, sa1[u]);
                sa1[u] = fma2(wv.y, xa1.y, sa1[u]);
                sp0[u] = fma2(wv.x, xp0.x, sp0[u]);
                sp0[u] = fma2(wv.y, xp0.y, sp0[u]);
                sp1[u] = fma2(wv.x, xp1.x, sp1[u]);
                sp1[u] = fma2(wv.y, xp1.y, sp1[u]);
            }
        }
        float ea0[4], ea1[4], ep0[4], ep1[4];
        #pragma unroll
        for (int u = 0; u < 4; u++) {
            ea0[u] = hadd2(sa0[u]); ea1[u] = hadd2(sa1[u]);
            ep0[u] = hadd2(sp0[u]); ep1[u] = hadd2(sp1[u]);
        }
        // attention-scalar partials
        float4 wsrc = *(const float4*)&Wa[d0];
        float4 wdst = *(const float4*)&Wa[DD + d0];
        float4 a0 = make_float4(ea0[0], ea0[1], ea0[2], ea0[3]);
        float4 a1 = make_float4(ea1[0], ea1[1], ea1[2], ea1[3]);
        float ps0 = dot4(wsrc, a0, 0.0f), ps1 = dot4(wsrc, a1, 0.0f);
        float pd0 = dot4(wdst, a0, 0.0f), pd1 = dot4(wdst, a1, 0.0f);
        // tanh + delta, float4 swizzled stores
        {
            float4 t0, t1, dd0, dd1;
            t0.x = fast_tanh(ea0[0]); t0.y = fast_tanh(ea0[1]);
            t0.z = fast_tanh(ea0[2]); t0.w = fast_tanh(ea0[3]);
            t1.x = fast_tanh(ea1[0]); t1.y = fast_tanh(ea1[1]);
            t1.z = fast_tanh(ea1[2]); t1.w = fast_tanh(ea1[3]);
            dd0.x = fast_tanh(ep0[0]) - t0.x; dd0.y = fast_tanh(ep0[1]) - t0.y;
            dd0.z = fast_tanh(ep0[2]) - t0.z; dd0.w = fast_tanh(ep0[3]) - t0.w;
            dd1.x = fast_tanh(ep1[0]) - t1.x; dd1.y = fast_tanh(ep1[1]) - t1.y;
            dd1.z = fast_tanh(ep1[2]) - t1.z; dd1.w = fast_tanh(ep1[3]) - t1.w;
            *(float4*)&ta[n0 * E_S + (d0 ^ sw)] = t0;
            *(float4*)&ta[n1 * E_S + (d0 ^ sw)] = t1;
            *(float4*)&de[n0 * E_S + (d0 ^ sw)] = dd0;
            *(float4*)&de[n1 * E_S + (d0 ^ sw)] = dd1;
        }
        // reduce partials over the 4 lanes sharing np
        ps0 += __shfl_xor_sync(0xffffffffu, ps0, 8);
        ps0 += __shfl_xor_sync(0xffffffffu, ps0, 16);
        ps1 += __shfl_xor_sync(0xffffffffu, ps1, 8);
        ps1 += __shfl_xor_sync(0xffffffffu, ps1, 16);
        pd0 += __shfl_xor_sync(0xffffffffu, pd0, 8);
        pd0 += __shfl_xor_sync(0xffffffffu, pd0, 16);
        pd1 += __shfl_xor_sync(0xffffffffu, pd1, 8);
        pd1 += __shfl_xor_sync(0xffffffffu, pd1, 16);
        if ((t & 31) < 8) {
            atomicAdd(&ssrc[n0], ps0);
            atomicAdd(&ssrc[n1], ps1);
            atomicAdd(&sdst[n0], pd0);
            atomicAdd(&sdst[n1], pd1);
        }
    }
    __syncthreads();

    // ---- P2: parallel softmax + W1 float4 load ----
    {
        const int i = t >> 4, j = t & 15;
        float e = lrelu(ssrc[i] + sdst[j]);
        float mx = e;
        #pragma unroll
        for (int m = 8; m; m >>= 1)
            mx = fmaxf(mx, __shfl_xor_sync(0xffffffffu, mx, m));
        float ex = __expf(e - mx);
        float sum = ex;
        #pragma unroll
        for (int m = 8; m; m >>= 1)
            sum += __shfl_xor_sync(0xffffffffu, sum, m);
        float wv = __fdividef(ex, sum);
        w[i * WT_S + j] = wv * 0.0625f;   // store w/16; T,V stay unscaled
        if (write_w)
            out[BB * NN * NN + b * NN * NN + t] = wv;
    }
    #pragma unroll
    for (int i = 0; i < 12; i++) {
        int e = (t + i * 256) * 4;
        int r = e / NF, c = e - r * NF;
        *(float4*)&W1[r * W1_S + c] = *(const float4*)&g_W1[e];
    }
    __syncthreads();

    // ---- P3: split-K, 2n x 4h tiles, packed f32x2 d-loops ----
    {
        const int np = t & 7;
        const int n0 = np * 2, n1 = n0 + 1;
        const int h0 = ((t >> 3) & 15) * 4;
        const int sw = SW(n0);

        u64 at0[4], at1[4], av0[4], av1[4];
        #pragma unroll
        for (int u = 0; u < 4; u++) { at0[u] = 0ull; at1[u] = 0ull; av0[u] = 0ull; av1[u] = 0ull; }

        if (t < 128) {
            // group A: au over OBS (scalar) + T/V partials over d in [0,48)
            float au0[4], au1[4];
            #pragma unroll
            for (int u = 0; u < 4; u++) { au0[u] = 0.0f; au1[u] = 0.0f; }
            #pragma unroll
            for (int k = 0; k < OBS; k += 4) {
                float4 x0 = *(const float4*)&st[n0 * ST_S + (k ^ sw)];
                float4 x1 = *(const float4*)&st[n1 * ST_S + (k ^ sw)];
                #pragma unroll
                for (int u = 0; u < 4; u++) {
                    float4 wv = *(const float4*)&W1[(h0 + u) * W1_S + k];
                    au0[u] = dot4(wv, x0, au0[u]);
                    au1[u] = dot4(wv, x1, au1[u]);
                }
            }
            #pragma unroll
            for (int d = 0; d < 48; d += 4) {
                ulonglong2 xt0 = *(const ulonglong2*)&ta[n0 * E_S + (d ^ sw)];
                ulonglong2 xt1 = *(const ulonglong2*)&ta[n1 * E_S + (d ^ sw)];
                ulonglong2 xd0 = *(const ulonglong2*)&de[n0 * E_S + (d ^ sw)];
                ulonglong2 xd1 = *(const ulonglong2*)&de[n1 * E_S + (d ^ sw)];
                #pragma unroll
                for (int u = 0; u < 4; u++) {
                    ulonglong2 wv = *(const ulonglong2*)&W1[(h0 + u) * W1_S + OBS + d];
                    at0[u] = fma2(wv.x, xt0.x, at0[u]);
                    at0[u] = fma2(wv.y, xt0.y, at0[u]);
                    at1[u] = fma2(wv.x, xt1.x, at1[u]);
                    at1[u] = fma2(wv.y, xt1.y, at1[u]);
                    av0[u] = fma2(wv.x, xd0.x, av0[u]);
                    av0[u] = fma2(wv.y, xd0.y, av0[u]);
                    av1[u] = fma2(wv.x, xd1.x, av1[u]);
                    av1[u] = fma2(wv.y, xd1.y, av1[u]);
                }
            }
            float4 f;
            f.x = au0[0]; f.y = au0[1]; f.z = au0[2]; f.w = au0[3];
            *(float4*)&U[n0 * HV_S + h0] = f;
            f.x = au1[0]; f.y = au1[1]; f.z = au1[2]; f.w = au1[3];
            *(float4*)&U[n1 * HV_S + h0] = f;
            f.x = hadd2(at0[0]); f.y = hadd2(at0[1]); f.z = hadd2(at0[2]); f.w = hadd2(at0[3]);
            *(float4*)&T1[n0 * HV_S + h0] = f;
            f.x = hadd2(at1[0]); f.y = hadd2(at1[1]); f.z = hadd2(at1[2]); f.w = hadd2(at1[3]);
            *(float4*)&T1[n1 * HV_S + h0] = f;
            f.x = hadd2(av0[0]); f.y = hadd2(av0[1]); f.z = hadd2(av0[2]); f.w = hadd2(av0[3]);
            *(float4*)&V1[n0 * HV_S + h0] = f;
            f.x = hadd2(av1[0]); f.y = hadd2(av1[1]); f.z = hadd2(av1[2]); f.w = hadd2(av1[3]);
            *(float4*)&V1[n1 * HV_S + h0] = f;
        } else {
            // group B: T/V partials over d in [48,128)
            #pragma unroll
            for (int d = 48; d < DD; d += 4) {
                ulonglong2 xt0 = *(const ulonglong2*)&ta[n0 * E_S + (d ^ sw)];
                ulonglong2 xt1 = *(const ulonglong2*)&ta[n1 * E_S + (d ^ sw)];
                ulonglong2 xd0 = *(const ulonglong2*)&de[n0 * E_S + (d ^ sw)];
                ulonglong2 xd1 = *(const ulonglong2*)&de[n1 * E_S + (d ^ sw)];
                #pragma unroll
                for (int u = 0; u < 4; u++) {
                    ulonglong2 wv = *(const ulonglong2*)&W1[(h0 + u) * W1_S + OBS + d];
                    at0[u] = fma2(wv.x, xt0.x, at0[u]);
                    at0[u] = fma2(wv.y, xt0.y, at0[u]);
                    at1[u] = fma2(wv.x, xt1.x, at1[u]);
                    at1[u] = fma2(wv.y, xt1.y, at1[u]);
                    av0[u] = fma2(wv.x, xd0.x, av0[u]);
                    av0[u] = fma2(wv.y, xd0.y, av0[u]);
                    av1[u] = fma2(wv.x, xd1.x, av1[u]);
                    av1[u] = fma2(wv.y, xd1.y, av1[u]);
                }
            }
            float4 f;
            f.x = hadd2(at0[0]); f.y = hadd2(at0[1]); f.z = hadd2(at0[2]); f.w = hadd2(at0[3]);
            *(float4*)&T2[n0 * HV_S + h0] = f;
            f.x = hadd2(at1[0]); f.y = hadd2(at1[1]); f.z = hadd2(at1[2]); f.w = hadd2(at1[3]);
            *(float4*)&T2[n1 * HV_S + h0] = f;
            f.x = hadd2(av0[0]); f.y = hadd2(av0[1]); f.z = hadd2(av0[2]); f.w = hadd2(av0[3]);
            *(float4*)&V2[n0 * HV_S + h0] = f;
            f.x = hadd2(av1[0]); f.y = hadd2(av1[1]); f.z = hadd2(av1[2]); f.w = hadd2(av1[3]);
            *(float4*)&V2[n1 * HV_S + h0] = f;
        }
    }
    __syncthreads();

    // ---- P4a: U[n,h] = au + sum_j w'[n,j]*(T1+T2)[j,h]; combine V ----
    {
        const int pn = t & 15, ph0 = (t >> 4) * 4;
        float4 ua = *(const float4*)&U[pn * HV_S + ph0];
        float acc[4] = {ua.x, ua.y, ua.z, ua.w};
        #pragma unroll
        for (int j = 0; j < NN; j++) {
            float wv = w[pn * WT_S + j];
            float4 t1 = *(const float4*)&T1[j * HV_S + ph0];
            float4 t2 = *(const float4*)&T2[j * HV_S + ph0];
            acc[0] = fmaf(wv, t1.x, acc[0]); acc[0] = fmaf(wv, t2.x, acc[0]);
            acc[1] = fmaf(wv, t1.y, acc[1]); acc[1] = fmaf(wv, t2.y, acc[1]);
            acc[2] = fmaf(wv, t1.z, acc[2]); acc[2] = fmaf(wv, t2.z, acc[2]);
            acc[3] = fmaf(wv, t1.w, acc[3]); acc[3] = fmaf(wv, t2.w, acc[3]);
        }
        float4 uv; uv.x = acc[0]; uv.y = acc[1]; uv.z = acc[2]; uv.w = acc[3];
        *(float4*)&U[pn * HV_S + ph0] = uv;
        // combine V = V1 + V2
        float4 v1 = *(const float4*)&V1[pn * HV_S + ph0];
        float4 v2 = *(const float4*)&V2[pn * HV_S + ph0];
        v1.x += v2.x; v1.y += v2.y; v1.z += v2.z; v1.w += v2.w;
        *(float4*)&V1[pn * HV_S + ph0] = v1;
    }
    __syncthreads();

    // ---- P4b: value[b,i,j] = W2 . lrelu(U[i] + w'[i,j]*V[j]) ----
    {
        const int i = t >> 4, j = t & 15;
        float wv = w[i * WT_S + j];    // scaled w/16 pairs with unscaled V
        float acc = 0.0f;
        #pragma unroll
        for (int h = 0; h < HH; h += 4) {
            float4 u4 = *(const float4*)&U[i * HV_S + h];
            float4 v4 = *(const float4*)&V1[j * HV_S + h];
            float4 w2 = *(const float4*)&W2s[h];
            acc = fmaf(w2.x, lrelu(fmaf(wv, v4.x, u4.x)), acc);
            acc = fmaf(w2.y, lrelu(fmaf(wv, v4.y, u4.y)), acc);
            acc = fmaf(w2.z, lrelu(fmaf(wv, v4.z, u4.z)), acc);
            acc = fmaf(w2.w, lrelu(fmaf(wv, v4.w, u4.w)), acc);
        }
        out[b * NN * NN + t] = acc;
    }
}

extern "C" void kernel_launch(void* const* d_in, const int* in_sizes, int n_in,
                              void* d_out, int out_size) {
    const float* st = (const float*)d_in[0];
    const float* po = (const float*)d_in[1];
    const float* ac = (const float*)d_in[2];
    const float* We = (const float*)d_in[3];
    const float* Wa = (const float*)d_in[4];
    const float* W1 = (const float*)d_in[5];
    const float* W2 = (const float*)d_in[6];
    float* out = (float*)d_out;

    const int smem = SMEM_FLOATS * (int)sizeof(float);
    cudaFuncSetAttribute(gac_kernel, cudaFuncAttributeMaxDynamicSharedMemorySize, smem);

    int write_w = (out_size >= 2 * BB * NN * NN) ? 1 : 0;

    gac_kernel<<<BB, 256, smem>>>(st, po, ac, We, Wa, W1, W2, out, write_w);
}

// round 13
// speedup vs baseline: 1.0019x; 1.0019x over previous
#include <cuda_runtime.h>

// Shapes (fixed)
#define BB 256
#define NN 16
#define OBS 64
#define ACT 8
#define DD 128
#define HH 64
#define II 72
#define NF 192

// 16B-aligned padded strides (floats)
#define WE_S 76
#define W1_S 196
#define ST_S 68
#define AC_S 12
#define E_S  132
#define WT_S 17
#define HV_S 68

// bank swizzle: rows n>=8 get their column-quads XOR'd by 4 words (16B)
#define SW(n) (((n) & 8) >> 1)

// float offsets into dynamic smem (all float4-aligned)
#define OFF_WEU 0
#define SZ_WEU  12544                 /* max(128*76=9728, 64*196=12544) */
#define OFF_WA  (OFF_WEU + SZ_WEU)
#define OFF_W2  (OFF_WA + 2 * DD)
#define OFF_ST  (OFF_W2 + HH)
#define OFF_AC  (OFF_ST + NN * ST_S)
#define OFF_PO  (OFF_AC + NN * AC_S)
#define OFF_TA  (OFF_PO + NN * AC_S)
#define OFF_DE  (OFF_TA + NN * E_S)
#define OFF_W   (OFF_DE + NN * E_S)
#define OFF_T1  (OFF_W  + NN * WT_S)
#define OFF_V1  (OFF_T1 + NN * HV_S)
#define OFF_U   (OFF_V1 + NN * HV_S)
#define OFF_T2  (OFF_U  + NN * HV_S)
#define OFF_V2  (OFF_T2 + NN * HV_S)
#define OFF_SSRC (OFF_V2 + NN * HV_S)
#define OFF_SDST (OFF_SSRC + NN)
#define SMEM_FLOATS (OFF_SDST + NN)

__device__ __forceinline__ float lrelu(float x) {
    return fmaxf(x, 0.01f * x);
}

// HW tanh (MUFU.TANH, sm_75+): 1 instruction, abs err ~5e-4
__device__ __forceinline__ float fast_tanh(float x) {
    float r;
    asm("tanh.approx.f32 %0, %1;" : "=f"(r) : "f"(x));
    return r;
}

__device__ __forceinline__ float dot4(float4 a, float4 b, float acc) {
    acc = fmaf(a.x, b.x, acc);
    acc = fmaf(a.y, b.y, acc);
    acc = fmaf(a.z, b.z, acc);
    acc = fmaf(a.w, b.w, acc);
    return acc;
}

__global__ void __launch_bounds__(256, 2)
gac_kernel(const float* __restrict__ g_st, const float* __restrict__ g_po,
           const float* __restrict__ g_ac, const float* __restrict__ g_We,
           const float* __restrict__ g_Wa, const float* __restrict__ g_W1,
           const float* __restrict__ g_W2, float* __restrict__ out,
           int write_w)
{
    extern __shared__ float sm[];
    float* We  = sm + OFF_WEU;   // [128][76] phase 1
    float* W1  = sm + OFF_WEU;   // [64][196] phase 3+ (union)
    float* Wa  = sm + OFF_WA;
    float* W2s = sm + OFF_W2;
    float* st  = sm + OFF_ST;
    float* ac  = sm + OFF_AC;
    float* po  = sm + OFF_PO;
    float* ta  = sm + OFF_TA;
    float* de  = sm + OFF_DE;
    float* w   = sm + OFF_W;
    float* T1  = sm + OFF_T1;
    float* V1  = sm + OFF_V1;
    float* U   = sm + OFF_U;
    float* T2  = sm + OFF_T2;
    float* V2  = sm + OFF_V2;
    float* ssrc = sm + OFF_SSRC;
    float* sdst = sm + OFF_SDST;

    const int t = threadIdx.x;
    const int b = blockIdx.x;

    // ---- P0: cooperative float4 loads ----
    {
        #pragma unroll
        for (int i = 0; i < 9; i++) {
            int e = (t + i * 256) * 4;
            int r = e / II, c = e - r * II;
            *(float4*)&We[r * WE_S + c] = *(const float4*)&g_We[e];
        }
        if (t < 64) *(float4*)&Wa[t * 4] = *(const float4*)&g_Wa[t * 4];
        if (t < 16) *(float4*)&W2s[t * 4] = *(const float4*)&g_W2[t * 4];
        {
            int r = t >> 4, c = (t & 15) * 4;
            *(float4*)&st[r * ST_S + (c ^ SW(r))] = *(const float4*)&g_st[b * NN * OBS + t * 4];
        }
        if (t < 32) {
            int r = t >> 1, c = (t & 1) * 4;
            *(float4*)&ac[r * AC_S + c] = *(const float4*)&g_ac[b * NN * ACT + t * 4];
            *(float4*)&po[r * AC_S + c] = *(const float4*)&g_po[b * NN * ACT + t * 4];
        }
        if (t < NN) { ssrc[t] = 0.0f; sdst[t] = 0.0f; }
    }
    __syncthreads();

    // ---- P1: embeddings, 2n x 4d tiles ----
    {
        const int np = t & 7;
        const int n0 = np * 2, n1 = n0 + 1;
        const int d0 = (t >> 3) * 4;
        const int sw = SW(n0);

        float sa0[4], sa1[4], sp0[4], sp1[4];
        #pragma unroll
        for (int u = 0; u < 4; u++) { sa0[u] = 0.0f; sa1[u] = 0.0f; }
        #pragma unroll
        for (int k = 0; k < OBS; k += 4) {
            float4 x0 = *(const float4*)&st[n0 * ST_S + (k ^ sw)];
            float4 x1 = *(const float4*)&st[n1 * ST_S + (k ^ sw)];
            #pragma unroll
            for (int u = 0; u < 4; u++) {
                float4 wv = *(const float4*)&We[(d0 + u) * WE_S + k];
                sa0[u] = dot4(wv, x0, sa0[u]);
                sa1[u] = dot4(wv, x1, sa1[u]);
            }
        }
        #pragma unroll
        for (int u = 0; u < 4; u++) { sp0[u] = sa0[u]; sp1[u] = sa1[u]; }
        #pragma unroll
        for (int k = 0; k < ACT; k += 4) {
            float4 xa0 = *(const float4*)&ac[n0 * AC_S + k];
            float4 xa1 = *(const float4*)&ac[n1 * AC_S + k];
            float4 xp0 = *(const float4*)&po[n0 * AC_S + k];
            float4 xp1 = *(const float4*)&po[n1 * AC_S + k];
            #pragma unroll
            for (int u = 0; u < 4; u++) {
                float4 wv = *(const float4*)&We[(d0 + u) * WE_S + OBS + k];
                sa0[u] = dot4(wv, xa0, sa0[u]);
                sa1[u] = dot4(wv, xa1, sa1[u]);
                sp0[u] = dot4(wv, xp0, sp0[u]);
                sp1[u] = dot4(wv, xp1, sp1[u]);
            }
        }
        // attention-scalar partials
        float4 wsrc = *(const float4*)&Wa[d0];
        float4 wdst = *(const float4*)&Wa[DD + d0];
        float4 a0 = make_float4(sa0[0], sa0[1], sa0[2], sa0[3]);
        float4 a1 = make_float4(sa1[0], sa1[1], sa1[2], sa1[3]);
        float ps0 = dot4(wsrc, a0, 0.0f), ps1 = dot4(wsrc, a1, 0.0f);
        float pd0 = dot4(wdst, a0, 0.0f), pd1 = dot4(wdst, a1, 0.0f);
        // tanh + delta, float4 swizzled stores
        {
            float4 t0, t1, dd0, dd1;
            t0.x = fast_tanh(sa0[0]); t0.y = fast_tanh(sa0[1]);
            t0.z = fast_tanh(sa0[2]); t0.w = fast_tanh(sa0[3]);
            t1.x = fast_tanh(sa1[0]); t1.y = fast_tanh(sa1[1]);
            t1.z = fast_tanh(sa1[2]); t1.w = fast_tanh(sa1[3]);
            dd0.x = fast_tanh(sp0[0]) - t0.x; dd0.y = fast_tanh(sp0[1]) - t0.y;
            dd0.z = fast_tanh(sp0[2]) - t0.z; dd0.w = fast_tanh(sp0[3]) - t0.w;
            dd1.x = fast_tanh(sp1[0]) - t1.x; dd1.y = fast_tanh(sp1[1]) - t1.y;
            dd1.z = fast_tanh(sp1[2]) - t1.z; dd1.w = fast_tanh(sp1[3]) - t1.w;
            *(float4*)&ta[n0 * E_S + (d0 ^ sw)] = t0;
            *(float4*)&ta[n1 * E_S + (d0 ^ sw)] = t1;
            *(float4*)&de[n0 * E_S + (d0 ^ sw)] = dd0;
            *(float4*)&de[n1 * E_S + (d0 ^ sw)] = dd1;
        }
        // reduce partials over the 4 lanes sharing np (lane bits 3,4 = d-quad low bits)
        ps0 += __shfl_xor_sync(0xffffffffu, ps0, 8);
        ps0 += __shfl_xor_sync(0xffffffffu, ps0, 16);
        ps1 += __shfl_xor_sync(0xffffffffu, ps1, 8);
        ps1 += __shfl_xor_sync(0xffffffffu, ps1, 16);
        pd0 += __shfl_xor_sync(0xffffffffu, pd0, 8);
        pd0 += __shfl_xor_sync(0xffffffffu, pd0, 16);
        pd1 += __shfl_xor_sync(0xffffffffu, pd1, 8);
        pd1 += __shfl_xor_sync(0xffffffffu, pd1, 16);
        if ((t & 31) < 8) {
            atomicAdd(&ssrc[n0], ps0);
            atomicAdd(&ssrc[n1], ps1);
            atomicAdd(&sdst[n0], pd0);
            atomicAdd(&sdst[n1], pd1);
        }
    }
    __syncthreads();

    // ---- P2: parallel softmax + W1 float4 load ----
    {
        const int i = t >> 4, j = t & 15;
        float e = lrelu(ssrc[i] + sdst[j]);
        float mx = e;
        #pragma unroll
        for (int m = 8; m; m >>= 1)
            mx = fmaxf(mx, __shfl_xor_sync(0xffffffffu, mx, m));
        float ex = __expf(e - mx);
        float sum = ex;
        #pragma unroll
        for (int m = 8; m; m >>= 1)
            sum += __shfl_xor_sync(0xffffffffu, sum, m);
        float wv = __fdividef(ex, sum);
        w[i * WT_S + j] = wv * 0.0625f;   // store w/16; T,V stay unscaled
        if (write_w)
            out[BB * NN * NN + b * NN * NN + t] = wv;
    }
    #pragma unroll
    for (int i = 0; i < 12; i++) {
        int e = (t + i * 256) * 4;
        int r = e / NF, c = e - r * NF;
        *(float4*)&W1[r * W1_S + c] = *(const float4*)&g_W1[e];
    }
    __syncthreads();

    // ---- P3: split-K, 2n x 4h tiles ----
    {
        const int np = t & 7;
        const int n0 = np * 2, n1 = n0 + 1;
        const int h0 = ((t >> 3) & 15) * 4;
        const int sw = SW(n0);

        float at0[4], at1[4], av0[4], av1[4];
        #pragma unroll
        for (int u = 0; u < 4; u++) { at0[u] = 0.0f; at1[u] = 0.0f; av0[u] = 0.0f; av1[u] = 0.0f; }

        if (t < 128) {
            float au0[4], au1[4];
            #pragma unroll
            for (int u = 0; u < 4; u++) { au0[u] = 0.0f; au1[u] = 0.0f; }
            #pragma unroll
            for (int k = 0; k < OBS; k += 4) {
                float4 x0 = *(const float4*)&st[n0 * ST_S + (k ^ sw)];
                float4 x1 = *(const float4*)&st[n1 * ST_S + (k ^ sw)];
                #pragma unroll
                for (int u = 0; u < 4; u++) {
                    float4 wv = *(const float4*)&W1[(h0 + u) * W1_S + k];
                    au0[u] = dot4(wv, x0, au0[u]);
                    au1[u] = dot4(wv, x1, au1[u]);
                }
            }
            #pragma unroll
            for (int d = 0; d < 48; d += 4) {
                float4 xt0 = *(const float4*)&ta[n0 * E_S + (d ^ sw)];
                float4 xt1 = *(const float4*)&ta[n1 * E_S + (d ^ sw)];
                float4 xd0 = *(const float4*)&de[n0 * E_S + (d ^ sw)];
                float4 xd1 = *(const float4*)&de[n1 * E_S + (d ^ sw)];
                #pragma unroll
                for (int u = 0; u < 4; u++) {
                    float4 wv = *(const float4*)&W1[(h0 + u) * W1_S + OBS + d];
                    at0[u] = dot4(wv, xt0, at0[u]);
                    at1[u] = dot4(wv, xt1, at1[u]);
                    av0[u] = dot4(wv, xd0, av0[u]);
                    av1[u] = dot4(wv, xd1, av1[u]);
                }
            }
            float4 f;
            f.x = au0[0]; f.y = au0[1]; f.z = au0[2]; f.w = au0[3];
            *(float4*)&U[n0 * HV_S + h0] = f;
            f.x = au1[0]; f.y = au1[1]; f.z = au1[2]; f.w = au1[3];
            *(float4*)&U[n1 * HV_S + h0] = f;
            f.x = at0[0]; f.y = at0[1]; f.z = at0[2]; f.w = at0[3];
            *(float4*)&T1[n0 * HV_S + h0] = f;
            f.x = at1[0]; f.y = at1[1]; f.z = at1[2]; f.w = at1[3];
            *(float4*)&T1[n1 * HV_S + h0] = f;
            f.x = av0[0]; f.y = av0[1]; f.z = av0[2]; f.w = av0[3];
            *(float4*)&V1[n0 * HV_S + h0] = f;
            f.x = av1[0]; f.y = av1[1]; f.z = av1[2]; f.w = av1[3];
            *(float4*)&V1[n1 * HV_S + h0] = f;
        } else {
            #pragma unroll
            for (int d = 48; d < DD; d += 4) {
                float4 xt0 = *(const float4*)&ta[n0 * E_S + (d ^ sw)];
                float4 xt1 = *(const float4*)&ta[n1 * E_S + (d ^ sw)];
                float4 xd0 = *(const float4*)&de[n0 * E_S + (d ^ sw)];
                float4 xd1 = *(const float4*)&de[n1 * E_S + (d ^ sw)];
                #pragma unroll
                for (int u = 0; u < 4; u++) {
                    float4 wv = *(const float4*)&W1[(h0 + u) * W1_S + OBS + d];
                    at0[u] = dot4(wv, xt0, at0[u]);
                    at1[u] = dot4(wv, xt1, at1[u]);
                    av0[u] = dot4(wv, xd0, av0[u]);
                    av1[u] = dot4(wv, xd1, av1[u]);
                }
            }
            float4 f;
            f.x = at0[0]; f.y = at0[1]; f.z = at0[2]; f.w = at0[3];
            *(float4*)&T2[n0 * HV_S + h0] = f;
            f.x = at1[0]; f.y = at1[1]; f.z = at1[2]; f.w = at1[3];
            *(float4*)&T2[n1 * HV_S + h0] = f;
            f.x = av0[0]; f.y = av0[1]; f.z = av0[2]; f.w = av0[3];
            *(float4*)&V2[n0 * HV_S + h0] = f;
            f.x = av1[0]; f.y = av1[1]; f.z = av1[2]; f.w = av1[3];
            *(float4*)&V2[n1 * HV_S + h0] = f;
        }
    }
    __syncthreads();

    // ---- P4a: U[n,h] = au + sum_j w'[n,j]*(T1+T2)[j,h]; combine V ----
    {
        const int pn = t & 15, ph0 = (t >> 4) * 4;
        float4 ua = *(const float4*)&U[pn * HV_S + ph0];
        float acc[4] = {ua.x, ua.y, ua.z, ua.w};
        #pragma unroll
        for (int j = 0; j < NN; j++) {
            float wv = w[pn * WT_S + j];
            float4 t1 = *(const float4*)&T1[j * HV_S + ph0];
            float4 t2 = *(const float4*)&T2[j * HV_S + ph0];
            acc[0] = fmaf(wv, t1.x, acc[0]); acc[0] = fmaf(wv, t2.x, acc[0]);
            acc[1] = fmaf(wv, t1.y, acc[1]); acc[1] = fmaf(wv, t2.y, acc[1]);
            acc[2] = fmaf(wv, t1.z, acc[2]); acc[2] = fmaf(wv, t2.z, acc[2]);
            acc[3] = fmaf(wv, t1.w, acc[3]); acc[3] = fmaf(wv, t2.w, acc[3]);
        }
        float4 uv; uv.x = acc[0]; uv.y = acc[1]; uv.z = acc[2]; uv.w = acc[3];
        *(float4*)&U[pn * HV_S + ph0] = uv;
        // combine V = V1 + V2
        float4 v1 = *(const float4*)&V1[pn * HV_S + ph0];
        float4 v2 = *(const float4*)&V2[pn * HV_S + ph0];
        v1.x += v2.x; v1.y += v2.y; v1.z += v2.z; v1.w += v2.w;
        *(float4*)&V1[pn * HV_S + ph0] = v1;
    }
    __syncthreads();

    // ---- P4b: value[b,i,j] = W2 . lrelu(U[i] + w'[i,j]*V[j]) ----
    {
        const int i = t >> 4, j = t & 15;
        float wv = w[i * WT_S + j];    // scaled w/16 pairs with unscaled V
        float acc = 0.0f;
        #pragma unroll
        for (int h = 0; h < HH; h += 4) {
            float4 u4 = *(const float4*)&U[i * HV_S + h];
            float4 v4 = *(const float4*)&V1[j * HV_S + h];
            float4 w2 = *(const float4*)&W2s[h];
            acc = fmaf(w2.x, lrelu(fmaf(wv, v4.x, u4.x)), acc);
            acc = fmaf(w2.y, lrelu(fmaf(wv, v4.y, u4.y)), acc);
            acc = fmaf(w2.z, lrelu(fmaf(wv, v4.z, u4.z)), acc);
            acc = fmaf(w2.w, lrelu(fmaf(wv, v4.w, u4.w)), acc);
        }
        out[b * NN * NN + t] = acc;
    }
}

extern "C" void kernel_launch(void* const* d_in, const int* in_sizes, int n_in,
                              void* d_out, int out_size) {
    const float* st = (const float*)d_in[0];
    const float* po = (const float*)d_in[1];
    const float* ac = (const float*)d_in[2];
    const float* We = (const float*)d_in[3];
    const float* Wa = (const float*)d_in[4];
    const float* W1 = (const float*)d_in[5];
    const float* W2 = (const float*)d_in[6];
    float* out = (float*)d_out;

    const int smem = SMEM_FLOATS * (int)sizeof(float);
    cudaFuncSetAttribute(gac_kernel, cudaFuncAttributeMaxDynamicSharedMemorySize, smem);

    int write_w = (out_size >= 2 * BB * NN * NN) ? 1 : 0;

    gac_kernel<<<BB, 256, smem>>>(st, po, ac, We, Wa, W1, W2, out, write_w);
}